// round 11
// baseline (speedup 1.0000x reference)
#include <cuda_runtime.h>
#include <cstdint>

#define NN 100
#define DD 128
#define CH 2048
#define NEG_INF __int_as_float(0xff800000)

// per-batch table block in scratch AND decode smem (floats):
// K [128][104] @0   V [128][108] @13312   P [100][132] @27136   Q [100][132] @40336
#define OFF_K 0
#define OFF_V 13312
#define OFF_P 27136
#define OFF_Q 40336
#define TBLK  53536

struct Args { const void* p[10]; long sz[10]; int n; int batch; };

__device__ float g_scr[(size_t)CH * TBLK];   // ~438MB, zero-init
__device__ int g_psel, g_klen, g_ok, g_enc, g_widx[5];

// ---------------- f32x2 helpers ----------------
__device__ __forceinline__ void ffma2(unsigned long long &d, unsigned long long a, unsigned long long b){
    asm("fma.rn.f32x2 %0, %1, %2, %0;" : "+l"(d) : "l"(a), "l"(b));
}
__device__ __forceinline__ unsigned long long add2(unsigned long long a, unsigned long long b){
    unsigned long long r; asm("add.rn.f32x2 %0, %1, %2;" : "=l"(r) : "l"(a), "l"(b)); return r;
}
__device__ __forceinline__ unsigned long long dup2(float x){
    unsigned long long r; asm("mov.b64 %0, {%1, %1};" : "=l"(r) : "f"(x)); return r;
}
__device__ __forceinline__ void unpack2(unsigned long long v, float &lo, float &hi){
    asm("mov.b64 {%0, %1}, %2;" : "=f"(lo), "=f"(hi) : "l"(v));
}

// =====================================================================
// prep: device-side role detection by content. Guarded. (proven R9/R10)
// =====================================================================
__global__ void prep_kernel(Args a)
{
    if (threadIdx.x != 0) return;
    int ok = 1;

    int encIdx = 0; long mxs = -1;
    for (int i = 0; i < a.n; i++) if (a.sz[i] > mxs){ mxs = a.sz[i]; encIdx = i; }
    const long want = (long)a.batch * NN * DD;
    long scale = 1;
    if      (mxs == want)     scale = 1;
    else if (mxs == want * 4) scale = 4;
    else ok = 0;

    int psel = -1;
    for (int i = 0; i < a.n; i++){
        if (a.sz[i] / scale < 64) continue;
        const int* q = (const int*)a.p[i];
        bool good = true; int mn = 1 << 30, mxv = -1;
        for (int k = 0; k < 64; k++){
            const int v = q[k];
            if (v < 0 || v >= NN){ good = false; break; }
            mn = v < mn ? v : mn; mxv = v > mxv ? v : mxv;
        }
        if (good && mxv > mn){ psel = i; break; }
    }
    int klen = 10;
    if (psel >= 0 && a.batch > 0){
        const long kl = (a.sz[psel] / scale) / a.batch;
        if (kl >= 1 && kl <= NN) klen = (int)kl; else ok = 0;
    } else ok = 0;

    int prob = -1;
    for (int i = 0; i < a.n; i++){
        if (i == encIdx || i == psel) continue;
        if (a.sz[i] / scale == (long)DD * DD) continue;
        const float* f = (const float*)a.p[i];
        bool good = true;
        for (int k = 0; k < 64; k++){
            const float v = f[k];
            if (!(v > 0.f && v < 1.f)){ good = false; break; }
        }
        if (good){ prob = i; break; }
    }

    int w[10]; int nw = 0;
    for (int i = 0; i < a.n; i++)
        if (a.sz[i] / scale == (long)DD * DD && nw < 10) w[nw++] = i;
    if (nw != 5){ ok = 0; w[0]=2; w[1]=3; w[2]=4; w[3]=5; w[4]=6; }

    const bool dict = (prob < 0) ? true : (prob < encIdx);
    // roles: 0=Wq_first 1=Wq_last 2=Wk 3=Wv 4=Wcomb
    if (dict){ g_widx[0]=w[0]; g_widx[1]=w[1]; g_widx[2]=w[2]; g_widx[3]=w[3]; g_widx[4]=w[4]; }
    else     { g_widx[0]=w[2]; g_widx[1]=w[3]; g_widx[2]=w[1]; g_widx[3]=w[4]; g_widx[4]=w[0]; }

    g_psel = psel; g_klen = klen; g_enc = encIdx; g_ok = ok;
}

__global__ void prefill_kernel(Args a, float* __restrict__ out)
{
    const int b = blockIdx.x, tid = threadIdx.x;
    for (int j = tid; j < NN; j += blockDim.x) out[b*NN + j] = 1.0f;
    const int psel = g_psel, klen = g_klen;
    if (psel >= 0 && tid < klen){
        const int* pre = (const int*)a.p[psel];
        int p = pre[b*klen + tid];
        out[b*NN + tid] = (float)((p >= 0 && p < NN) ? p : 0);
    }
}

// =====================================================================
// gemm: grid (chunk, 4); 256 threads; f32x2 FMA core. (proven R10)
// =====================================================================
__global__ __launch_bounds__(256, 2) void gemm_kernel(Args a, int c0)
{
    if (!g_ok) return;
    __shared__ __align__(16) float Es[32*102 + 16];
    __shared__ __align__(16) float Ws[32*132];
    __shared__ __align__(16) float q1s[128];

    const int bb = blockIdx.x, m = blockIdx.y;
    const int b = c0 + bb;
    const int tid = threadIdx.x;
    const int tx = tid & 31;
    const int ty = tid >> 5;

    const int role = (m==0) ? 2 : (m==1) ? 1 : (m==2) ? 3 : 4;
    const float* W   = (const float*)a.p[g_widx[role]];
    const float* enc = (const float*)a.p[g_enc];
    const float* Eb  = enc + (size_t)b * (NN*DD);
    const int klen = g_klen;

    if (m == 1 && tid < 128){
        const int* pre = (const int*)a.p[g_psel];
        int last = pre[b*klen + (klen-1)];
        last = (last >= 0 && last < NN) ? last : 0;
        const float* er = Eb + last*DD;
        const float* Wqf = (const float*)a.p[g_widx[0]];
        float s = 0.f;
        for (int d = 0; d < DD; d++) s += er[d] * Wqf[d*DD + tid];
        q1s[tid] = s;
    }

    unsigned long long acc[7][4];
    #pragma unroll
    for (int k = 0; k < 7; k++){ acc[k][0]=0ull; acc[k][1]=0ull; acc[k][2]=0ull; acc[k][3]=0ull; }

    for (int dch = 0; dch < 4; dch++){
        const int d0 = dch * 32;
        __syncthreads();
        for (int e = tid; e < 3200; e += 256){
            const int n = e >> 5, dd = e & 31;
            Es[dd*102 + n] = Eb[n*DD + d0 + dd];
        }
        if (m < 3){
            for (int e = tid; e < 4096; e += 256){
                const int dd = e >> 7, c = e & 127;
                Ws[dd*132 + c] = W[(d0+dd)*DD + c];
            }
        } else {
            for (int e = tid; e < 4096; e += 256){
                const int c = e >> 5, dd = e & 31;
                Ws[dd*132 + c] = W[c*DD + d0 + dd];
            }
        }
        __syncthreads();

        #pragma unroll 4
        for (int dd = 0; dd < 32; dd++){
            const float4 w4 = *(const float4*)(Ws + dd*132 + 4*tx);
            const unsigned long long w0 = dup2(w4.x), w1 = dup2(w4.y),
                                     w2 = dup2(w4.z), w3 = dup2(w4.w);
            const float* er = Es + dd*102 + 2*ty;
            #pragma unroll
            for (int k = 0; k < 7; k++){
                const unsigned long long e2 = *(const unsigned long long*)(er + 16*k);
                ffma2(acc[k][0], e2, w0);
                ffma2(acc[k][1], e2, w1);
                ffma2(acc[k][2], e2, w2);
                ffma2(acc[k][3], e2, w3);
            }
        }
    }
    __syncthreads();

    float* base = g_scr + (size_t)bb * TBLK;
    float4 q1v = make_float4(0.f,0.f,0.f,0.f);
    if (m == 1) q1v = *(const float4*)(q1s + 4*tx);

    #pragma unroll
    for (int k = 0; k < 7; k++){
        const int n0 = 2*(ty + 8*k);
        if (n0 >= NN) continue;
        const int n1 = n0 + 1;
        float lo0,hi0,lo1,hi1,lo2,hi2,lo3,hi3;
        unpack2(acc[k][0], lo0, hi0);
        unpack2(acc[k][1], lo1, hi1);
        unpack2(acc[k][2], lo2, hi2);
        unpack2(acc[k][3], lo3, hi3);
        if (m == 0){
            float* K = base + OFF_K;
            K[(4*tx+0)*104 + n0] = lo0;  K[(4*tx+0)*104 + n1] = hi0;
            K[(4*tx+1)*104 + n0] = lo1;  K[(4*tx+1)*104 + n1] = hi1;
            K[(4*tx+2)*104 + n0] = lo2;  K[(4*tx+2)*104 + n1] = hi2;
            K[(4*tx+3)*104 + n0] = lo3;  K[(4*tx+3)*104 + n1] = hi3;
        } else if (m == 2){
            float* V = base + OFF_V;
            V[(4*tx+0)*108 + n0] = lo0;  V[(4*tx+0)*108 + n1] = hi0;
            V[(4*tx+1)*108 + n0] = lo1;  V[(4*tx+1)*108 + n1] = hi1;
            V[(4*tx+2)*108 + n0] = lo2;  V[(4*tx+2)*108 + n1] = hi2;
            V[(4*tx+3)*108 + n0] = lo3;  V[(4*tx+3)*108 + n1] = hi3;
        } else if (m == 3){
            float* P = base + OFF_P;
            *(float4*)(P + n0*132 + 4*tx) = make_float4(lo0,lo1,lo2,lo3);
            *(float4*)(P + n1*132 + 4*tx) = make_float4(hi0,hi1,hi2,hi3);
        } else {
            float* Q = base + OFF_Q;
            *(float4*)(Q + n0*132 + 4*tx) = make_float4(lo0+q1v.x, lo1+q1v.y, lo2+q1v.z, lo3+q1v.w);
            *(float4*)(Q + n1*132 + 4*tx) = make_float4(hi0+q1v.x, hi1+q1v.y, hi2+q1v.z, hi3+q1v.w);
        }
    }
}

// =====================================================================
// decode: 3 phases / 4 barriers per step.
//  A: scores -> exp (no max-sub) -> Z -> att normalized in-place
//  C: psum halves of att·V
//  DE: per-n (100 thr) psum-combine + P-dot + tanh + 2-level argmax
// =====================================================================
__global__ __launch_bounds__(256, 1) void decode_kernel(Args a, int c0, float* __restrict__ out)
{
    if (!g_ok || g_psel < 0) return;
    extern __shared__ __align__(16) float sm[];
    float* Kt    = sm + OFF_K;           // [128][104]
    float* Vt    = sm + OFF_V;           // [128][108]
    float* Pt    = sm + OFF_P;           // [100][132]
    float* Qt    = sm + OFF_Q;           // [100][132]
    float* att   = sm + TBLK;            // [8][112]
    float* psum  = att + 8*112;          // [2][128]
    float* maskv = psum + 256;           // [104]
    float* candv = maskv + 104;          // [8]
    int*   candi = (int*)(candv + 8);    // [8]
    int*   icur  = (int*)(candi + 8);

    const int bb = blockIdx.x;
    const int b  = c0 + bb;
    const int tid = threadIdx.x;
    const int lane = tid & 31, wid = tid >> 5;
    const int klen = g_klen;
    const int* pre = (const int*)a.p[g_psel];

    {
        const float4* src = (const float4*)(g_scr + (size_t)bb * TBLK);
        float4* dst = (float4*)sm;
        for (int i = tid; i < TBLK/4; i += 256) dst[i] = src[i];
    }
    if (tid < 104) maskv[tid] = 0.f;
    __syncthreads();
    if (tid < klen){
        int p = pre[b*klen + tid];
        p = (p >= 0 && p < NN) ? p : 0;
        maskv[p] = NEG_INF;
        out[b*NN + tid] = (float)p;
    }
    if (tid == 0){
        int last = pre[b*klen + (klen-1)];
        icur[0] = (last >= 0 && last < NN) ? last : 0;
    }
    __syncthreads();

    // phase-C constants
    const int cC = tid & 127, halfC = tid >> 7;
    const int nqBeg = halfC ? 13 : 0, nqEnd = halfC ? 25 : 13;
    const float* VrowC = Vt + cC*108;
    const float* arC   = att + (cC >> 4)*112;

    const int steps = NN - klen;
    for (int step = 0; step < steps; step++){
        const int cur = icur[0];

        // ---- Phase A: scores, exp (no max-sub), Z, normalized att ----
        {
            const int h = wid;
            const int nq = (lane < 25) ? lane : 24;
            const bool valid = (lane < 25);
            const float* qrow = Qt + cur*132 + h*16;      // 16B aligned
            const float* kq = Kt + (h*16)*104 + 4*nq;
            unsigned long long a0 = 0ull, a1 = 0ull;
            #pragma unroll
            for (int eq = 0; eq < 4; eq++){
                const float4 q4 = *(const float4*)(qrow + 4*eq);
                const unsigned long long qa = dup2(q4.x), qb = dup2(q4.y),
                                         qc = dup2(q4.z), qd = dup2(q4.w);
                const float* kp = kq + (4*eq)*104;
                ulonglong2 k2;
                k2 = *(const ulonglong2*)(kp);        ffma2(a0, qa, k2.x); ffma2(a1, qa, k2.y);
                k2 = *(const ulonglong2*)(kp + 104);  ffma2(a0, qb, k2.x); ffma2(a1, qb, k2.y);
                k2 = *(const ulonglong2*)(kp + 208);  ffma2(a0, qc, k2.x); ffma2(a1, qc, k2.y);
                k2 = *(const ulonglong2*)(kp + 312);  ffma2(a0, qd, k2.x); ffma2(a1, qd, k2.y);
            }
            float s0,s1,s2,s3;
            unpack2(a0, s0, s1);
            unpack2(a1, s2, s3);
            const float4 m4 = *(const float4*)(maskv + 4*nq);
            float w0 = 0.f, w1 = 0.f, w2 = 0.f, w3 = 0.f;
            if (valid){
                w0 = expf(s0*0.25f + m4.x);   // expf(-inf)=0 handles mask
                w1 = expf(s1*0.25f + m4.y);
                w2 = expf(s2*0.25f + m4.z);
                w3 = expf(s3*0.25f + m4.w);
            }
            float zs = (w0+w1) + (w2+w3);
            #pragma unroll
            for (int o = 16; o; o >>= 1) zs += __shfl_xor_sync(0xffffffffu, zs, o);
            const float rz = 1.0f / zs;
            if (valid) *(float4*)(att + h*112 + 4*nq) = make_float4(w0*rz, w1*rz, w2*rz, w3*rz);
        }
        __syncthreads();

        // ---- Phase C: psum halves of att·V ----
        {
            unsigned long long a0 = 0ull, a1 = 0ull;
            for (int nq = nqBeg; nq < nqEnd; nq++){
                const ulonglong2 av = *(const ulonglong2*)(arC + 4*nq);
                const ulonglong2 vv = *(const ulonglong2*)(VrowC + 4*nq);
                ffma2(a0, av.x, vv.x);
                ffma2(a1, av.y, vv.y);
            }
            float s0,s1,s2,s3;
            unpack2(a0, s0, s1);
            unpack2(a1, s2, s3);
            psum[halfC*128 + cC] = (s0+s1) + (s2+s3);
        }
        __syncthreads();

        // ---- Phase DE: per-n dot + tanh + warp argmax ----
        if (tid < 128){
            const int n = tid;
            float v = NEG_INF;
            if (n < NN){
                const float* Prow = Pt + n*132;
                unsigned long long a0 = 0ull, a1 = 0ull;
                #pragma unroll 8
                for (int jq = 0; jq < 32; jq += 2){
                    const ulonglong2 pA0 = *(const ulonglong2*)(psum + 4*jq);
                    const ulonglong2 pB0 = *(const ulonglong2*)(psum + 128 + 4*jq);
                    const ulonglong2 pq0 = *(const ulonglong2*)(Prow + 4*jq);
                    ffma2(a0, add2(pA0.x, pB0.x), pq0.x);
                    ffma2(a1, add2(pA0.y, pB0.y), pq0.y);
                    const ulonglong2 pA1 = *(const ulonglong2*)(psum + 4*jq + 4);
                    const ulonglong2 pB1 = *(const ulonglong2*)(psum + 132 + 4*jq);
                    const ulonglong2 pq1 = *(const ulonglong2*)(Prow + 4*jq + 4);
                    ffma2(a0, add2(pA1.x, pB1.x), pq1.x);
                    ffma2(a1, add2(pA1.y, pB1.y), pq1.y);
                }
                float s0,s1,s2,s3;
                unpack2(a0, s0, s1);
                unpack2(a1, s2, s3);
                const float sc = ((s0+s1) + (s2+s3)) * 0.08838834764831845f; // 1/sqrt(128)
                v = 10.f * tanhf(sc) + maskv[n];
            }
            float best = v; int bi = (n < NN) ? n : 127;
            #pragma unroll
            for (int o = 16; o; o >>= 1){
                const float ov = __shfl_down_sync(0xffffffffu, best, o);
                const int   oi = __shfl_down_sync(0xffffffffu, bi,   o);
                if (ov > best || (ov == best && oi < bi)){ best = ov; bi = oi; }
            }
            if (lane == 0){ candv[wid] = best; candi[wid] = bi; }
        }
        __syncthreads();
        if (tid == 0){
            float best = candv[0]; int bi = candi[0];
            #pragma unroll
            for (int w = 1; w < 4; w++){
                const float ov = candv[w]; const int oi = candi[w];
                if (ov > best || (ov == best && oi < bi)){ best = ov; bi = oi; }
            }
            maskv[bi] = NEG_INF;
            icur[0] = bi;
            out[b*NN + klen + step] = (float)bi;
        }
        __syncthreads();
    }
}

// =====================================================================
extern "C" void kernel_launch(void* const* d_in, const int* in_sizes, int n_in,
                              void* d_out, int out_size)
{
    Args a;
    for (int i = 0; i < 10; i++){
        a.p[i]  = (i < n_in) ? d_in[i] : d_in[0];
        a.sz[i] = (i < n_in) ? (long)in_sizes[i] : 0;
    }
    a.n = (n_in < 10) ? n_in : 10;
    a.batch = out_size / NN;
    if (a.batch < 1) a.batch = 1;
    float* out = (float*)d_out;

    prep_kernel<<<1, 32>>>(a);
    prefill_kernel<<<a.batch, 128>>>(a, out);

    const int smem_bytes = (TBLK + 8*112 + 256 + 104 + 8 + 8 + 4) * 4;
    (void)cudaFuncSetAttribute(decode_kernel, cudaFuncAttributeMaxDynamicSharedMemorySize, smem_bytes);

    for (int c0 = 0; c0 < a.batch; c0 += CH){
        const int cb = (a.batch - c0 < CH) ? (a.batch - c0) : CH;
        dim3 g(cb, 4);
        gemm_kernel<<<g, 256>>>(a, c0);
        decode_kernel<<<cb, 256, smem_bytes>>>(a, c0, out);
    }
}